// round 1
// baseline (speedup 1.0000x reference)
#include <cuda_runtime.h>
#include <cstdint>
#include <cstddef>

// Problem dims (fixed per reference)
#define BB 256
#define TT 512
#define II 64
#define HH 128
#define GG 512   // 4*H

// Scratch for precomputed input-gate projections: [B, T, 4H] fp32 = 256 MB.
// __device__ global = the sanctioned scratch mechanism (no cudaMalloc).
__device__ float g_xg[(size_t)BB * TT * GG];

__device__ __forceinline__ float fsig(float x) {
    // 1 / (1 + e^-x); __expf(inf)->inf, __fdividef(1,inf)->0 : saturates correctly
    return __fdividef(1.f, 1.f + __expf(-x));
}
__device__ __forceinline__ float ftanh(float x) {
    // 1 - 2/(e^{2x}+1); saturates to +/-1 without NaNs at large |x|
    float e = __expf(2.f * x);
    return 1.f - __fdividef(2.f, e + 1.f);
}

// ---------------------------------------------------------------------------
// Kernel 1: x_gates[b,t,g] = sum_i X[b,t,i] * W_ih[g,i] + (b_ih[g] + b_hh[g])
// GEMM: M = B*T = 131072, N = 512, K = 64. Register tiled 8x8 per thread.
// Block tile: M=64, N=512 (full), K=64 (full). 512 threads.
// ---------------------------------------------------------------------------
__global__ __launch_bounds__(512, 1) void xg_gemm(
    const float* __restrict__ X,
    const float* __restrict__ Wih,
    const float* __restrict__ bih,
    const float* __restrict__ bhh)
{
    extern __shared__ float sm[];
    float* Xs = sm;                 // [64][68]  (pad 68: conflict-free + 16B aligned)
    float* Ws = sm + 64 * 68;       // [64][516] (pad 516)
    float* bs = Ws + 64 * 516;      // [512]
    const int tid = threadIdx.x;
    const int m0  = blockIdx.x * 64;

    bs[tid] = bih[tid] + bhh[tid];

    // Stage X tile transposed -> Xs[k][m]
    for (int idx = tid; idx < 64 * 64; idx += 512) {
        int m = idx >> 6, k = idx & 63;
        Xs[k * 68 + m] = X[(size_t)(m0 + m) * II + k];
    }
    // Stage W_ih transposed -> Ws[k][n]
    for (int idx = tid; idx < 512 * 64; idx += 512) {
        int n = idx >> 6, k = idx & 63;
        Ws[k * 516 + n] = Wih[n * II + k];
    }
    __syncthreads();

    const int ni = tid & 63, mi = tid >> 6;   // 64 n-groups x 8 m-groups
    const int nb = ni * 8,  mb = mi * 8;

    float acc[8][8];
    #pragma unroll
    for (int n = 0; n < 8; n++) {
        float bv = bs[nb + n];
        #pragma unroll
        for (int m = 0; m < 8; m++) acc[m][n] = bv;
    }

    #pragma unroll 8
    for (int k = 0; k < 64; k++) {
        float4 a0 = *(const float4*)&Xs[k * 68 + mb];
        float4 a1 = *(const float4*)&Xs[k * 68 + mb + 4];
        float4 b0 = *(const float4*)&Ws[k * 516 + nb];
        float4 b1 = *(const float4*)&Ws[k * 516 + nb + 4];
        float a[8] = {a0.x, a0.y, a0.z, a0.w, a1.x, a1.y, a1.z, a1.w};
        float b[8] = {b0.x, b0.y, b0.z, b0.w, b1.x, b1.y, b1.z, b1.w};
        #pragma unroll
        for (int m = 0; m < 8; m++)
            #pragma unroll
            for (int n = 0; n < 8; n++)
                acc[m][n] += a[m] * b[n];
    }

    #pragma unroll
    for (int m = 0; m < 8; m++) {
        size_t row = (size_t)(m0 + mb + m);
        float4* o = (float4*)&g_xg[row * GG + nb];
        o[0] = make_float4(acc[m][0], acc[m][1], acc[m][2], acc[m][3]);
        o[1] = make_float4(acc[m][4], acc[m][5], acc[m][6], acc[m][7]);
    }
}

// ---------------------------------------------------------------------------
// Kernel 2: LSTM scan. 128 blocks x 512 threads; block handles batch pair
// (2*bid, 2*bid+1) for all 512 timesteps — no inter-block sync needed.
// Thread g owns gate row g: W_hh[g,0:64] in registers, W_hh[g,64:128] in smem
// (k-major, float2-packed per 2 k's). h for both batch elems lives in smem
// interleaved {h0[j], h1[j]} -> one float4 broadcast covers 2 k x 2 batches.
// ---------------------------------------------------------------------------
__global__ __launch_bounds__(512, 1) void lstm_scan(
    const float* __restrict__ hprev,
    const float* __restrict__ cprev,
    const float* __restrict__ Whh,
    float* __restrict__ out)
{
    extern __shared__ float sm[];
    float2* wsh = (float2*)sm;            // [32][512]: {W[g,64+2kk], W[g,65+2kk]}
    float*  hb  = sm + 32 * 512 * 2;      // [256] interleaved {h_b0[j], h_b1[j]}
    float*  gsm = hb + 256;               // [2][512] gate preactivations

    const int tid = threadIdx.x;
    const int b0  = blockIdx.x * 2;

    // Stage smem half of W_hh (one time)
    for (int idx = tid; idx < 32 * 512; idx += 512) {
        int kk = idx >> 9, g = idx & 511;
        wsh[idx] = *(const float2*)&Whh[g * HH + 64 + 2 * kk];
    }

    // Register half of W_hh: row g = tid, k = 0..63
    float wr[64];
    #pragma unroll
    for (int k = 0; k < 64; k++) wr[k] = Whh[tid * HH + k];

    // Init h, c
    float c = 0.f;
    if (tid < 256) {
        int b = tid >> 7, j = tid & 127;
        hb[j * 2 + b] = hprev[(b0 + b) * HH + j];
        c = cprev[(b0 + b) * HH + j];
    }
    __syncthreads();

    const float* xg0 = g_xg + (size_t)b0 * TT * GG;
    const float* xg1 = g_xg + (size_t)(b0 + 1) * TT * GG;

    for (int t = 0; t < TT; t++) {
        // ---- phase A: all 512 threads compute gate preactivations ----
        float x0 = xg0[(size_t)t * GG + tid];   // issued early, consumed late
        float x1 = xg1[(size_t)t * GG + tid];
        float a0 = 0.f, a1 = 0.f;

        #pragma unroll
        for (int kk = 0; kk < 32; kk++) {       // k = 2kk, 2kk+1 (register weights)
            float4 h4 = *(const float4*)&hb[4 * kk];
            a0 += wr[2 * kk]     * h4.x;
            a1 += wr[2 * kk]     * h4.y;
            a0 += wr[2 * kk + 1] * h4.z;
            a1 += wr[2 * kk + 1] * h4.w;
        }
        #pragma unroll
        for (int kk = 32; kk < 64; kk++) {      // k = 64..127 (smem weights)
            float4 h4 = *(const float4*)&hb[4 * kk];
            float2 w  = wsh[(kk - 32) * 512 + tid];
            a0 += w.x * h4.x;
            a1 += w.x * h4.y;
            a0 += w.y * h4.z;
            a1 += w.y * h4.w;
        }
        gsm[tid]       = x0 + a0;
        gsm[512 + tid] = x1 + a1;
        __syncthreads();

        // ---- phase B: threads 0..255 do the elementwise LSTM cell update ----
        if (tid < 256) {
            int b = tid >> 7, j = tid & 127;
            const float* gb = gsm + b * 512;
            float ig = fsig(gb[j]);             // PyTorch gate order: i, f, g, o
            float fg = fsig(gb[j + 128]);
            float gg = ftanh(gb[j + 256]);
            float og = fsig(gb[j + 384]);
            c = fg * c + ig * gg;
            float h = og * ftanh(c);
            hb[j * 2 + b] = h;
            out[((size_t)(b0 + b) * TT + t) * HH + j] = h;
        }
        __syncthreads();
    }

    // h_last, c_last appended after outputs
    if (tid < 256) {
        int b = tid >> 7, j = tid & 127;
        size_t base = (size_t)BB * TT * HH;
        out[base + (b0 + b) * HH + j] = hb[j * 2 + b];
        out[base + (size_t)BB * HH + (b0 + b) * HH + j] = c;
    }
}

// ---------------------------------------------------------------------------
extern "C" void kernel_launch(void* const* d_in, const int* in_sizes, int n_in,
                              void* d_out, int out_size)
{
    const float* inputs = (const float*)d_in[0];
    const float* hprev  = (const float*)d_in[1];
    const float* cprev  = (const float*)d_in[2];
    const float* Wih    = (const float*)d_in[3];
    const float* Whh    = (const float*)d_in[4];
    const float* bih    = (const float*)d_in[5];
    const float* bhh    = (const float*)d_in[6];
    float* out = (float*)d_out;
    (void)in_sizes; (void)n_in; (void)out_size;

    const size_t smem1 = (size_t)(64 * 68 + 64 * 516 + 512) * sizeof(float);   // ~148 KB
    const size_t smem2 = (size_t)(32 * 512 * 2 + 256 + 1024) * sizeof(float);  // ~133 KB
    cudaFuncSetAttribute(xg_gemm,  cudaFuncAttributeMaxDynamicSharedMemorySize, (int)smem1);
    cudaFuncSetAttribute(lstm_scan, cudaFuncAttributeMaxDynamicSharedMemorySize, (int)smem2);

    xg_gemm  <<<2048, 512, smem1>>>(inputs, Wih, bih, bhh);
    lstm_scan<<<128,  512, smem2>>>(hprev, cprev, Whh, out);
}

// round 2
// speedup vs baseline: 1.0495x; 1.0495x over previous
#include <cuda_runtime.h>
#include <cstdint>
#include <cstddef>

// Problem dims (fixed per reference)
#define BB 256
#define TT 512
#define II 64
#define HH 128
#define GG 512   // 4*H

typedef unsigned long long ull;

// Scratch for precomputed input-gate projections: [B, T, 4H] fp32 = 256 MB.
__device__ float g_xg[(size_t)BB * TT * GG];

__device__ __forceinline__ float fsig(float x) {
    return __fdividef(1.f, 1.f + __expf(-x));
}
__device__ __forceinline__ float ftanh(float x) {
    float e = __expf(2.f * x);
    return 1.f - __fdividef(2.f, e + 1.f);
}

// Packed f32x2 FMA / ADD (sm_103a; ptxas won't auto-fuse these)
__device__ __forceinline__ ull fma2(ull a, ull b, ull c) {
    ull d;
    asm("fma.rn.f32x2 %0, %1, %2, %3;" : "=l"(d) : "l"(a), "l"(b), "l"(c));
    return d;
}
__device__ __forceinline__ ull add2(ull a, ull b) {
    ull d;
    asm("add.rn.f32x2 %0, %1, %2;" : "=l"(d) : "l"(a), "l"(b));
    return d;
}
__device__ __forceinline__ float hsum2(ull a) {
    uint2 u = *reinterpret_cast<uint2*>(&a);
    return __uint_as_float(u.x) + __uint_as_float(u.y);
}

// ---------------------------------------------------------------------------
// Kernel 1: x_gates GEMM (unchanged from R1 — ~100us, revisit later if it binds)
// ---------------------------------------------------------------------------
__global__ __launch_bounds__(512, 1) void xg_gemm(
    const float* __restrict__ X,
    const float* __restrict__ Wih,
    const float* __restrict__ bih,
    const float* __restrict__ bhh)
{
    extern __shared__ __align__(16) float sm[];
    float* Xs = sm;                 // [64][68]
    float* Ws = sm + 64 * 68;       // [64][516]
    float* bs = Ws + 64 * 516;      // [512]
    const int tid = threadIdx.x;
    const int m0  = blockIdx.x * 64;

    bs[tid] = bih[tid] + bhh[tid];

    for (int idx = tid; idx < 64 * 64; idx += 512) {
        int m = idx >> 6, k = idx & 63;
        Xs[k * 68 + m] = X[(size_t)(m0 + m) * II + k];
    }
    for (int idx = tid; idx < 512 * 64; idx += 512) {
        int n = idx >> 6, k = idx & 63;
        Ws[k * 516 + n] = Wih[n * II + k];
    }
    __syncthreads();

    const int ni = tid & 63, mi = tid >> 6;
    const int nb = ni * 8,  mb = mi * 8;

    float acc[8][8];
    #pragma unroll
    for (int n = 0; n < 8; n++) {
        float bv = bs[nb + n];
        #pragma unroll
        for (int m = 0; m < 8; m++) acc[m][n] = bv;
    }

    #pragma unroll 8
    for (int k = 0; k < 64; k++) {
        float4 a0 = *(const float4*)&Xs[k * 68 + mb];
        float4 a1 = *(const float4*)&Xs[k * 68 + mb + 4];
        float4 b0 = *(const float4*)&Ws[k * 516 + nb];
        float4 b1 = *(const float4*)&Ws[k * 516 + nb + 4];
        float a[8] = {a0.x, a0.y, a0.z, a0.w, a1.x, a1.y, a1.z, a1.w};
        float b[8] = {b0.x, b0.y, b0.z, b0.w, b1.x, b1.y, b1.z, b1.w};
        #pragma unroll
        for (int m = 0; m < 8; m++)
            #pragma unroll
            for (int n = 0; n < 8; n++)
                acc[m][n] += a[m] * b[n];
    }

    #pragma unroll
    for (int m = 0; m < 8; m++) {
        size_t row = (size_t)(m0 + mb + m);
        float4* o = (float4*)&g_xg[row * GG + nb];
        o[0] = make_float4(acc[m][0], acc[m][1], acc[m][2], acc[m][3]);
        o[1] = make_float4(acc[m][4], acc[m][5], acc[m][6], acc[m][7]);
    }
}

// ---------------------------------------------------------------------------
// Kernel 2: LSTM scan, f32x2-packed.
// 128 blocks x 512 threads; block owns batch pair (2*bid, 2*bid+1) for all T.
// Thread g owns gate row g. Weight split: k 0..87 in registers as 44 packed
// f32x2 pairs; k 88..127 in smem as packed pairs (20 x 512 float2 = 80KB).
// h kept as two separate smem arrays (one per batch) so ulonglong2 loads give
// packed {h[2k], h[2k+1]} operands directly. 4 independent accumulator chains.
// ---------------------------------------------------------------------------
#define KREG 88                 // k-values held in registers (44 pairs)
#define KSH  ((HH - KREG) / 2)  // 20 smem weight pairs

__global__ __launch_bounds__(512, 1) void lstm_scan(
    const float* __restrict__ hprev,
    const float* __restrict__ cprev,
    const float* __restrict__ Whh,
    float* __restrict__ out)
{
    extern __shared__ __align__(16) float sm[];
    float2* ws   = (float2*)sm;               // [KSH pairs][512 gates]
    const ull* ws64 = (const ull*)sm;
    float* h0s = sm + KSH * 512 * 2;          // [128]
    float* h1s = h0s + 128;                   // [128]
    float* gsm = h1s + 128;                   // [2][512]

    const int tid = threadIdx.x;
    const int b0  = blockIdx.x * 2;

    // Stage smem weight pairs: ws[p][g] = {Whh[g, KREG+2p], Whh[g, KREG+2p+1]}
    for (int idx = tid; idx < KSH * 512; idx += 512) {
        int p = idx >> 9, g = idx & 511;
        ws[idx] = *(const float2*)&Whh[g * HH + KREG + 2 * p];
    }

    // Register weight pairs: wr[p] = packed {Whh[g,2p], Whh[g,2p+1]}
    ull wr[KREG / 2];
    #pragma unroll
    for (int p = 0; p < KREG / 2; p++)
        wr[p] = *(const ull*)&Whh[tid * HH + 2 * p];

    // Init h, c
    float c = 0.f;
    if (tid < 256) {
        int b = tid >> 7, j = tid & 127;
        float* hs = b ? h1s : h0s;
        hs[j] = hprev[(b0 + b) * HH + j];
        c = cprev[(b0 + b) * HH + j];
    }
    __syncthreads();

    const float* xg0 = g_xg + (size_t)b0 * TT * GG;
    const float* xg1 = g_xg + (size_t)(b0 + 1) * TT * GG;

    for (int t = 0; t < TT; t++) {
        // x loads issued early, consumed ~1000 cyc later (latency hidden)
        float x0 = xg0[(size_t)t * GG + tid];
        float x1 = xg1[(size_t)t * GG + tid];

        ull acc0a = 0, acc0b = 0, acc1a = 0, acc1b = 0;

        // k = 0..KREG-1 : register weights, 4 f32x2 values per float4 of h
        #pragma unroll
        for (int q = 0; q < KREG / 4; q++) {
            ulonglong2 hv0 = *(const ulonglong2*)&h0s[4 * q];
            ulonglong2 hv1 = *(const ulonglong2*)&h1s[4 * q];
            acc0a = fma2(wr[2 * q],     hv0.x, acc0a);
            acc0b = fma2(wr[2 * q + 1], hv0.y, acc0b);
            acc1a = fma2(wr[2 * q],     hv1.x, acc1a);
            acc1b = fma2(wr[2 * q + 1], hv1.y, acc1b);
        }
        // k = KREG..127 : smem weights (one load serves both batches)
        #pragma unroll
        for (int q = 0; q < KSH / 2; q++) {
            ulonglong2 hv0 = *(const ulonglong2*)&h0s[KREG + 4 * q];
            ulonglong2 hv1 = *(const ulonglong2*)&h1s[KREG + 4 * q];
            ull w0 = ws64[(2 * q) * 512 + tid];
            ull w1 = ws64[(2 * q + 1) * 512 + tid];
            acc0a = fma2(w0, hv0.x, acc0a);
            acc0b = fma2(w1, hv0.y, acc0b);
            acc1a = fma2(w0, hv1.x, acc1a);
            acc1b = fma2(w1, hv1.y, acc1b);
        }

        gsm[tid]       = x0 + hsum2(add2(acc0a, acc0b));
        gsm[512 + tid] = x1 + hsum2(add2(acc1a, acc1b));
        __syncthreads();

        // Cell update: 256 threads, one (batch, cell) each
        if (tid < 256) {
            int b = tid >> 7, j = tid & 127;
            const float* gb = gsm + b * 512;
            float ig = fsig(gb[j]);             // PyTorch order: i, f, g, o
            float fg = fsig(gb[j + 128]);
            float gg = ftanh(gb[j + 256]);
            float og = fsig(gb[j + 384]);
            c = fg * c + ig * gg;
            float h = og * ftanh(c);
            (b ? h1s : h0s)[j] = h;
            out[((size_t)(b0 + b) * TT + t) * HH + j] = h;
        }
        __syncthreads();
    }

    if (tid < 256) {
        int b = tid >> 7, j = tid & 127;
        size_t base = (size_t)BB * TT * HH;
        out[base + (b0 + b) * HH + j] = (b ? h1s : h0s)[j];
        out[base + (size_t)BB * HH + (b0 + b) * HH + j] = c;
    }
}

// ---------------------------------------------------------------------------
extern "C" void kernel_launch(void* const* d_in, const int* in_sizes, int n_in,
                              void* d_out, int out_size)
{
    const float* inputs = (const float*)d_in[0];
    const float* hprev  = (const float*)d_in[1];
    const float* cprev  = (const float*)d_in[2];
    const float* Wih    = (const float*)d_in[3];
    const float* Whh    = (const float*)d_in[4];
    const float* bih    = (const float*)d_in[5];
    const float* bhh    = (const float*)d_in[6];
    float* out = (float*)d_out;
    (void)in_sizes; (void)n_in; (void)out_size;

    const size_t smem1 = (size_t)(64 * 68 + 64 * 516 + 512) * sizeof(float);      // ~148 KB
    const size_t smem2 = (size_t)(KSH * 512 * 2 + 256 + 1024) * sizeof(float);    // ~85 KB
    cudaFuncSetAttribute(xg_gemm,   cudaFuncAttributeMaxDynamicSharedMemorySize, (int)smem1);
    cudaFuncSetAttribute(lstm_scan, cudaFuncAttributeMaxDynamicSharedMemorySize, (int)smem2);

    xg_gemm  <<<2048, 512, smem1>>>(inputs, Wih, bih, bhh);
    lstm_scan<<<128,  512, smem2>>>(hprev, cprev, Whh, out);
}

// round 3
// speedup vs baseline: 1.3480x; 1.2844x over previous
#include <cuda_runtime.h>
#include <cstdint>
#include <cstddef>

// Problem dims (fixed per reference)
#define BB 256
#define TT 512
#define II 64
#define HH 128
#define GG 512   // 4*H

typedef unsigned long long ull;

// Scratch for precomputed input-gate projections: [B, T, 4H] fp32 = 256 MB.
__device__ float g_xg[(size_t)BB * TT * GG];

__device__ __forceinline__ float fsig(float x) {
    return __fdividef(1.f, 1.f + __expf(-x));
}
__device__ __forceinline__ float ftanh(float x) {
    float e = __expf(2.f * x);
    return 1.f - __fdividef(2.f, e + 1.f);
}

// Packed f32x2 FMA / ADD (sm_103a; ptxas won't auto-fuse these)
__device__ __forceinline__ ull fma2(ull a, ull b, ull c) {
    ull d;
    asm("fma.rn.f32x2 %0, %1, %2, %3;" : "=l"(d) : "l"(a), "l"(b), "l"(c));
    return d;
}
__device__ __forceinline__ ull add2(ull a, ull b) {
    ull d;
    asm("add.rn.f32x2 %0, %1, %2;" : "=l"(d) : "l"(a), "l"(b));
    return d;
}
__device__ __forceinline__ float hsum2(ull a) {
    uint2 u = *reinterpret_cast<uint2*>(&a);
    return __uint_as_float(u.x) + __uint_as_float(u.y);
}

// ---------------------------------------------------------------------------
// Kernel 1: x_gates GEMM (unchanged — optimize next round with its profile)
// ---------------------------------------------------------------------------
__global__ __launch_bounds__(512, 1) void xg_gemm(
    const float* __restrict__ X,
    const float* __restrict__ Wih,
    const float* __restrict__ bih,
    const float* __restrict__ bhh)
{
    extern __shared__ __align__(16) float sm[];
    float* Xs = sm;                 // [64][68]
    float* Ws = sm + 64 * 68;       // [64][516]
    float* bs = Ws + 64 * 516;      // [512]
    const int tid = threadIdx.x;
    const int m0  = blockIdx.x * 64;

    bs[tid] = bih[tid] + bhh[tid];

    for (int idx = tid; idx < 64 * 64; idx += 512) {
        int m = idx >> 6, k = idx & 63;
        Xs[k * 68 + m] = X[(size_t)(m0 + m) * II + k];
    }
    for (int idx = tid; idx < 512 * 64; idx += 512) {
        int n = idx >> 6, k = idx & 63;
        Ws[k * 516 + n] = Wih[n * II + k];
    }
    __syncthreads();

    const int ni = tid & 63, mi = tid >> 6;
    const int nb = ni * 8,  mb = mi * 8;

    float acc[8][8];
    #pragma unroll
    for (int n = 0; n < 8; n++) {
        float bv = bs[nb + n];
        #pragma unroll
        for (int m = 0; m < 8; m++) acc[m][n] = bv;
    }

    #pragma unroll 8
    for (int k = 0; k < 64; k++) {
        float4 a0 = *(const float4*)&Xs[k * 68 + mb];
        float4 a1 = *(const float4*)&Xs[k * 68 + mb + 4];
        float4 b0 = *(const float4*)&Ws[k * 516 + nb];
        float4 b1 = *(const float4*)&Ws[k * 516 + nb + 4];
        float a[8] = {a0.x, a0.y, a0.z, a0.w, a1.x, a1.y, a1.z, a1.w};
        float b[8] = {b0.x, b0.y, b0.z, b0.w, b1.x, b1.y, b1.z, b1.w};
        #pragma unroll
        for (int m = 0; m < 8; m++)
            #pragma unroll
            for (int n = 0; n < 8; n++)
                acc[m][n] += a[m] * b[n];
    }

    #pragma unroll
    for (int m = 0; m < 8; m++) {
        size_t row = (size_t)(m0 + mb + m);
        float4* o = (float4*)&g_xg[row * GG + nb];
        o[0] = make_float4(acc[m][0], acc[m][1], acc[m][2], acc[m][3]);
        o[1] = make_float4(acc[m][4], acc[m][5], acc[m][6], acc[m][7]);
    }
}

// ---------------------------------------------------------------------------
// Kernel 2: LSTM scan. 128 blocks x 256 threads (8 warps); block owns batch
// pair (2*bid, 2*bid+1) for all T. Thread owns TWO gate rows: tid and tid+256.
// Weight split per gate: k 0..87 in registers (44 packed f32x2), k 88..127 in
// smem (10 ulonglong2 per gate per thread). h broadcast from smem as packed
// pairs; each h load feeds both gates. 8 independent f32x2 accumulator chains.
// ---------------------------------------------------------------------------
#define KREG 88                  // k-values per gate held in registers
#define QSH  10                  // (128-KREG)/4 : ulonglong2 smem weight loads

__global__ __launch_bounds__(256, 1) void lstm_scan(
    const float* __restrict__ hprev,
    const float* __restrict__ cprev,
    const float* __restrict__ Whh,
    float* __restrict__ out)
{
    extern __shared__ __align__(16) float sm[];
    ulonglong2* wA = (ulonglong2*)sm;            // [QSH][256]
    ulonglong2* wB = wA + QSH * 256;             // [QSH][256]
    float* h0s = (float*)(wB + QSH * 256);       // [128]
    float* h1s = h0s + 128;                      // [128]
    float* gsm = h1s + 128;                      // [2][512]

    const int tid = threadIdx.x;
    const int b0  = blockIdx.x * 2;
    const int gA  = tid;
    const int gB  = tid + 256;

    // Stage smem weight tail (k = KREG..127) for both gates
    #pragma unroll
    for (int q = 0; q < QSH; q++) {
        wA[q * 256 + tid] = *(const ulonglong2*)&Whh[gA * HH + KREG + 4 * q];
        wB[q * 256 + tid] = *(const ulonglong2*)&Whh[gB * HH + KREG + 4 * q];
    }

    // Register weights: 44 packed pairs per gate
    ull wrA[KREG / 2], wrB[KREG / 2];
    #pragma unroll
    for (int p = 0; p < KREG / 2; p++) {
        wrA[p] = *(const ull*)&Whh[gA * HH + 2 * p];
        wrB[p] = *(const ull*)&Whh[gB * HH + 2 * p];
    }

    // Init h, c : thread owns (b = tid>>7, j = tid&127)
    const int b = tid >> 7, j = tid & 127;
    float* hs = b ? h1s : h0s;
    hs[j] = hprev[(b0 + b) * HH + j];
    float c = cprev[(b0 + b) * HH + j];
    __syncthreads();

    const float* xb0 = g_xg + (size_t)b0 * TT * GG;
    const float* xb1 = xb0 + (size_t)TT * GG;

    // Prefetch t=0 x values
    float x00 = xb0[tid], x01 = xb0[256 + tid];
    float x10 = xb1[tid], x11 = xb1[256 + tid];

    for (int t = 0; t < TT; t++) {
        // Prefetch next step's x (hide L2/DRAM latency under the fma loop)
        size_t noff = (size_t)(t + 1 < TT ? t + 1 : t) * GG;
        float n00 = xb0[noff + tid], n01 = xb0[noff + 256 + tid];
        float n10 = xb1[noff + tid], n11 = xb1[noff + 256 + tid];

        // 8 accumulator chains: {gate A,B} x {batch 0,1} x {even,odd pair}
        ull aA0x = 0, aA0y = 0, aA1x = 0, aA1y = 0;
        ull aB0x = 0, aB0y = 0, aB1x = 0, aB1y = 0;

        // k = 0..KREG-1 : register weights
        #pragma unroll
        for (int q = 0; q < KREG / 4; q++) {
            ulonglong2 h0 = *(const ulonglong2*)&h0s[4 * q];
            ulonglong2 h1 = *(const ulonglong2*)&h1s[4 * q];
            ull w0 = wrA[2 * q], w1 = wrA[2 * q + 1];
            ull v0 = wrB[2 * q], v1 = wrB[2 * q + 1];
            aA0x = fma2(w0, h0.x, aA0x);  aA0y = fma2(w1, h0.y, aA0y);
            aA1x = fma2(w0, h1.x, aA1x);  aA1y = fma2(w1, h1.y, aA1y);
            aB0x = fma2(v0, h0.x, aB0x);  aB0y = fma2(v1, h0.y, aB0y);
            aB1x = fma2(v0, h1.x, aB1x);  aB1y = fma2(v1, h1.y, aB1y);
        }
        // k = KREG..127 : smem weights
        #pragma unroll
        for (int q = 0; q < QSH; q++) {
            ulonglong2 h0 = *(const ulonglong2*)&h0s[KREG + 4 * q];
            ulonglong2 h1 = *(const ulonglong2*)&h1s[KREG + 4 * q];
            ulonglong2 wa = wA[q * 256 + tid];
            ulonglong2 wb = wB[q * 256 + tid];
            aA0x = fma2(wa.x, h0.x, aA0x);  aA0y = fma2(wa.y, h0.y, aA0y);
            aA1x = fma2(wa.x, h1.x, aA1x);  aA1y = fma2(wa.y, h1.y, aA1y);
            aB0x = fma2(wb.x, h0.x, aB0x);  aB0y = fma2(wb.y, h0.y, aB0y);
            aB1x = fma2(wb.x, h1.x, aB1x);  aB1y = fma2(wb.y, h1.y, aB1y);
        }

        gsm[tid]             = x00 + hsum2(add2(aA0x, aA0y));
        gsm[256 + tid]       = x01 + hsum2(add2(aB0x, aB0y));
        gsm[512 + tid]       = x10 + hsum2(add2(aA1x, aA1y));
        gsm[512 + 256 + tid] = x11 + hsum2(add2(aB1x, aB1y));
        __syncthreads();

        // Cell update: all 256 threads, one (batch, cell) each
        {
            const float* gb = gsm + b * 512;
            float ig = fsig(gb[j]);             // PyTorch order: i, f, g, o
            float fg = fsig(gb[j + 128]);
            float gg = ftanh(gb[j + 256]);
            float og = fsig(gb[j + 384]);
            c = fg * c + ig * gg;
            float h = og * ftanh(c);
            hs[j] = h;
            out[((size_t)(b0 + b) * TT + t) * HH + j] = h;
        }
        __syncthreads();

        x00 = n00; x01 = n01; x10 = n10; x11 = n11;
    }

    // h_last, c_last appended after outputs
    {
        size_t base = (size_t)BB * TT * HH;
        out[base + (b0 + b) * HH + j] = hs[j];
        out[base + (size_t)BB * HH + (b0 + b) * HH + j] = c;
    }
}

// ---------------------------------------------------------------------------
extern "C" void kernel_launch(void* const* d_in, const int* in_sizes, int n_in,
                              void* d_out, int out_size)
{
    const float* inputs = (const float*)d_in[0];
    const float* hprev  = (const float*)d_in[1];
    const float* cprev  = (const float*)d_in[2];
    const float* Wih    = (const float*)d_in[3];
    const float* Whh    = (const float*)d_in[4];
    const float* bih    = (const float*)d_in[5];
    const float* bhh    = (const float*)d_in[6];
    float* out = (float*)d_out;
    (void)in_sizes; (void)n_in; (void)out_size;

    const size_t smem1 = (size_t)(64 * 68 + 64 * 516 + 512) * sizeof(float);        // ~148 KB
    const size_t smem2 = (size_t)(2 * QSH * 256) * sizeof(ulonglong2)
                       + (size_t)(256 + 1024) * sizeof(float);                      // ~85 KB
    cudaFuncSetAttribute(xg_gemm,   cudaFuncAttributeMaxDynamicSharedMemorySize, (int)smem1);
    cudaFuncSetAttribute(lstm_scan, cudaFuncAttributeMaxDynamicSharedMemorySize, (int)smem2);

    xg_gemm  <<<2048, 512, smem1>>>(inputs, Wih, bih, bhh);
    lstm_scan<<<128,  256, smem2>>>(hprev, cprev, Whh, out);
}

// round 4
// speedup vs baseline: 1.3834x; 1.0263x over previous
#include <cuda_runtime.h>
#include <cstdint>
#include <cstddef>

// Problem dims (fixed per reference)
#define BB 256
#define TT 512
#define II 64
#define HH 128
#define GG 512   // 4*H

typedef unsigned long long ull;

// Scratch for precomputed input-gate projections: [B, T, 4H] fp32 = 256 MB.
__device__ float g_xg[(size_t)BB * TT * GG];

__device__ __forceinline__ float fsig(float x) {
    return __fdividef(1.f, 1.f + __expf(-x));
}
__device__ __forceinline__ float ftanh(float x) {
    float e = __expf(2.f * x);
    return 1.f - __fdividef(2.f, e + 1.f);
}

// Packed f32x2 ops (sm_103a; ptxas never auto-fuses these)
__device__ __forceinline__ ull fma2(ull a, ull b, ull c) {
    ull d;
    asm("fma.rn.f32x2 %0, %1, %2, %3;" : "=l"(d) : "l"(a), "l"(b), "l"(c));
    return d;
}
__device__ __forceinline__ ull add2(ull a, ull b) {
    ull d;
    asm("add.rn.f32x2 %0, %1, %2;" : "=l"(d) : "l"(a), "l"(b));
    return d;
}
__device__ __forceinline__ ull pack2(float x, float y) {
    ull r;
    asm("mov.b64 %0, {%1, %2};" : "=l"(r) : "f"(x), "f"(y));
    return r;
}
__device__ __forceinline__ float hsum2(ull a) {
    uint2 u = *reinterpret_cast<uint2*>(&a);
    return __uint_as_float(u.x) + __uint_as_float(u.y);
}
__device__ __forceinline__ float lo2(ull a) { return __uint_as_float((unsigned)a); }
__device__ __forceinline__ float hi2(ull a) { return __uint_as_float((unsigned)(a >> 32)); }

// ---------------------------------------------------------------------------
// Kernel 1: x_gates GEMM, f32x2-packed (m-pairs in accumulator).
// M = B*T = 131072, N = 512, K = 64. Block tile 64(M) x 512(N), 512 threads,
// 8x8 per thread -> 4 m-pair x 8 n fma2 accumulators.
// ---------------------------------------------------------------------------
__global__ __launch_bounds__(512, 1) void xg_gemm(
    const float* __restrict__ X,
    const float* __restrict__ Wih,
    const float* __restrict__ bih,
    const float* __restrict__ bhh)
{
    extern __shared__ __align__(16) float sm[];
    float* Xs = sm;                 // [64][68]  (m-contiguous rows)
    float* Ws = sm + 64 * 68;       // [64][516]
    float* bs = Ws + 64 * 516;      // [512]
    const int tid = threadIdx.x;
    const int m0  = blockIdx.x * 64;

    bs[tid] = bih[tid] + bhh[tid];

    for (int idx = tid; idx < 64 * 64; idx += 512) {
        int m = idx >> 6, k = idx & 63;
        Xs[k * 68 + m] = X[(size_t)(m0 + m) * II + k];
    }
    for (int idx = tid; idx < 512 * 64; idx += 512) {
        int n = idx >> 6, k = idx & 63;
        Ws[k * 516 + n] = Wih[n * II + k];
    }
    __syncthreads();

    const int ni = tid & 63, mi = tid >> 6;
    const int nb = ni * 8,  mb = mi * 8;

    // acc2[mp][n] : packed {m=2mp, m=2mp+1} for column nb+n
    ull acc2[4][8];
    #pragma unroll
    for (int n = 0; n < 8; n++) {
        float bv = bs[nb + n];
        ull bp = pack2(bv, bv);
        #pragma unroll
        for (int mp = 0; mp < 4; mp++) acc2[mp][n] = bp;
    }

    #pragma unroll 4
    for (int k = 0; k < 64; k++) {
        // a: 4 packed m-pairs (Xs rows are m-contiguous, 16B-aligned at mb)
        ulonglong2 a01 = *(const ulonglong2*)&Xs[k * 68 + mb];
        ulonglong2 a23 = *(const ulonglong2*)&Xs[k * 68 + mb + 4];
        ull a[4] = {a01.x, a01.y, a23.x, a23.y};
        float4 b0 = *(const float4*)&Ws[k * 516 + nb];
        float4 b1 = *(const float4*)&Ws[k * 516 + nb + 4];
        float bv[8] = {b0.x, b0.y, b0.z, b0.w, b1.x, b1.y, b1.z, b1.w};
        #pragma unroll
        for (int n = 0; n < 8; n++) {
            ull bb = pack2(bv[n], bv[n]);
            #pragma unroll
            for (int mp = 0; mp < 4; mp++)
                acc2[mp][n] = fma2(a[mp], bb, acc2[mp][n]);
        }
    }

    #pragma unroll
    for (int mp = 0; mp < 4; mp++) {
        size_t row0 = (size_t)(m0 + mb + 2 * mp);
        float4* o0 = (float4*)&g_xg[row0 * GG + nb];
        float4* o1 = (float4*)&g_xg[(row0 + 1) * GG + nb];
        o0[0] = make_float4(lo2(acc2[mp][0]), lo2(acc2[mp][1]), lo2(acc2[mp][2]), lo2(acc2[mp][3]));
        o0[1] = make_float4(lo2(acc2[mp][4]), lo2(acc2[mp][5]), lo2(acc2[mp][6]), lo2(acc2[mp][7]));
        o1[0] = make_float4(hi2(acc2[mp][0]), hi2(acc2[mp][1]), hi2(acc2[mp][2]), hi2(acc2[mp][3]));
        o1[1] = make_float4(hi2(acc2[mp][4]), hi2(acc2[mp][5]), hi2(acc2[mp][6]), hi2(acc2[mp][7]));
    }
}

// ---------------------------------------------------------------------------
// Kernel 2: LSTM scan. 128 blocks x 256 threads; block owns batch pair.
// Thread owns gates tid and tid+256. KREG=80 k-values per gate in registers
// (160 regs) — deliberately below the 254 cap so ptxas has ~40 spare regs to
// software-pipeline the smem load stream (R3 was latency-bound at the cap).
// ---------------------------------------------------------------------------
#define KREG 80                  // k-values per gate held in registers
#define QSH  12                  // (128-KREG)/4 : ulonglong2 smem weight loads

__global__ __launch_bounds__(256, 1) void lstm_scan(
    const float* __restrict__ hprev,
    const float* __restrict__ cprev,
    const float* __restrict__ Whh,
    float* __restrict__ out)
{
    extern __shared__ __align__(16) float sm[];
    ulonglong2* wA = (ulonglong2*)sm;            // [QSH][256]
    ulonglong2* wB = wA + QSH * 256;             // [QSH][256]
    float* h0s = (float*)(wB + QSH * 256);       // [128]
    float* h1s = h0s + 128;                      // [128]
    float* gsm = h1s + 128;                      // [2][512]

    const int tid = threadIdx.x;
    const int b0  = blockIdx.x * 2;
    const int gA  = tid;
    const int gB  = tid + 256;

    // Stage smem weight tail (k = KREG..127) for both gates
    #pragma unroll
    for (int q = 0; q < QSH; q++) {
        wA[q * 256 + tid] = *(const ulonglong2*)&Whh[gA * HH + KREG + 4 * q];
        wB[q * 256 + tid] = *(const ulonglong2*)&Whh[gB * HH + KREG + 4 * q];
    }

    // Register weights: 40 packed pairs per gate
    ull wrA[KREG / 2], wrB[KREG / 2];
    #pragma unroll
    for (int p = 0; p < KREG / 2; p++) {
        wrA[p] = *(const ull*)&Whh[gA * HH + 2 * p];
        wrB[p] = *(const ull*)&Whh[gB * HH + 2 * p];
    }

    // Init h, c : thread owns (b = tid>>7, j = tid&127)
    const int b = tid >> 7, j = tid & 127;
    float* hs = b ? h1s : h0s;
    hs[j] = hprev[(b0 + b) * HH + j];
    float c = cprev[(b0 + b) * HH + j];
    __syncthreads();

    const float* xb0 = g_xg + (size_t)b0 * TT * GG;
    const float* xb1 = xb0 + (size_t)TT * GG;

    // Prefetch t=0 x values
    float x00 = xb0[tid], x01 = xb0[256 + tid];
    float x10 = xb1[tid], x11 = xb1[256 + tid];

    for (int t = 0; t < TT; t++) {
        // Prefetch next step's x (consumed ~1 step later; hides DRAM latency)
        size_t noff = (size_t)(t + 1 < TT ? t + 1 : t) * GG;
        float n00 = xb0[noff + tid], n01 = xb0[noff + 256 + tid];
        float n10 = xb1[noff + tid], n11 = xb1[noff + 256 + tid];

        // 8 accumulator chains: {gate A,B} x {batch 0,1} x {even,odd pair}
        ull aA0x = 0, aA0y = 0, aA1x = 0, aA1y = 0;
        ull aB0x = 0, aB0y = 0, aB1x = 0, aB1y = 0;

        // k = 0..KREG-1 : register weights
        #pragma unroll
        for (int q = 0; q < KREG / 4; q++) {
            ulonglong2 h0 = *(const ulonglong2*)&h0s[4 * q];
            ulonglong2 h1 = *(const ulonglong2*)&h1s[4 * q];
            ull w0 = wrA[2 * q], w1 = wrA[2 * q + 1];
            ull v0 = wrB[2 * q], v1 = wrB[2 * q + 1];
            aA0x = fma2(w0, h0.x, aA0x);  aA0y = fma2(w1, h0.y, aA0y);
            aA1x = fma2(w0, h1.x, aA1x);  aA1y = fma2(w1, h1.y, aA1y);
            aB0x = fma2(v0, h0.x, aB0x);  aB0y = fma2(v1, h0.y, aB0y);
            aB1x = fma2(v0, h1.x, aB1x);  aB1y = fma2(v1, h1.y, aB1y);
        }
        // k = KREG..127 : smem weights
        #pragma unroll
        for (int q = 0; q < QSH; q++) {
            ulonglong2 h0 = *(const ulonglong2*)&h0s[KREG + 4 * q];
            ulonglong2 h1 = *(const ulonglong2*)&h1s[KREG + 4 * q];
            ulonglong2 wa = wA[q * 256 + tid];
            ulonglong2 wb = wB[q * 256 + tid];
            aA0x = fma2(wa.x, h0.x, aA0x);  aA0y = fma2(wa.y, h0.y, aA0y);
            aA1x = fma2(wa.x, h1.x, aA1x);  aA1y = fma2(wa.y, h1.y, aA1y);
            aB0x = fma2(wb.x, h0.x, aB0x);  aB0y = fma2(wb.y, h0.y, aB0y);
            aB1x = fma2(wb.x, h1.x, aB1x);  aB1y = fma2(wb.y, h1.y, aB1y);
        }

        gsm[tid]             = x00 + hsum2(add2(aA0x, aA0y));
        gsm[256 + tid]       = x01 + hsum2(add2(aB0x, aB0y));
        gsm[512 + tid]       = x10 + hsum2(add2(aA1x, aA1y));
        gsm[512 + 256 + tid] = x11 + hsum2(add2(aB1x, aB1y));
        __syncthreads();

        // Cell update: all 256 threads, one (batch, cell) each
        {
            const float* gb = gsm + b * 512;
            float ig = fsig(gb[j]);             // PyTorch order: i, f, g, o
            float fg = fsig(gb[j + 128]);
            float gg = ftanh(gb[j + 256]);
            float og = fsig(gb[j + 384]);
            c = fg * c + ig * gg;
            float h = og * ftanh(c);
            hs[j] = h;
            out[((size_t)(b0 + b) * TT + t) * HH + j] = h;
        }
        __syncthreads();

        x00 = n00; x01 = n01; x10 = n10; x11 = n11;
    }

    // h_last, c_last appended after outputs
    {
        size_t base = (size_t)BB * TT * HH;
        out[base + (b0 + b) * HH + j] = hs[j];
        out[base + (size_t)BB * HH + (b0 + b) * HH + j] = c;
    }
}

// ---------------------------------------------------------------------------
extern "C" void kernel_launch(void* const* d_in, const int* in_sizes, int n_in,
                              void* d_out, int out_size)
{
    const float* inputs = (const float*)d_in[0];
    const float* hprev  = (const float*)d_in[1];
    const float* cprev  = (const float*)d_in[2];
    const float* Wih    = (const float*)d_in[3];
    const float* Whh    = (const float*)d_in[4];
    const float* bih    = (const float*)d_in[5];
    const float* bhh    = (const float*)d_in[6];
    float* out = (float*)d_out;
    (void)in_sizes; (void)n_in; (void)out_size;

    const size_t smem1 = (size_t)(64 * 68 + 64 * 516 + 512) * sizeof(float);        // ~148 KB
    const size_t smem2 = (size_t)(2 * QSH * 256) * sizeof(ulonglong2)
                       + (size_t)(256 + 1024) * sizeof(float);                      // ~103 KB
    cudaFuncSetAttribute(xg_gemm,   cudaFuncAttributeMaxDynamicSharedMemorySize, (int)smem1);
    cudaFuncSetAttribute(lstm_scan, cudaFuncAttributeMaxDynamicSharedMemorySize, (int)smem2);

    xg_gemm  <<<2048, 512, smem1>>>(inputs, Wih, bih, bhh);
    lstm_scan<<<128,  256, smem2>>>(hprev, cprev, Whh, out);
}